// round 14
// baseline (speedup 1.0000x reference)
#include <cuda_runtime.h>
#include <cuda_fp16.h>
#include <cstdint>

#define NN    1024
#define QSZ   256
#define BOT   40

// ------------------------- scratch (no allocs allowed) -----------------------
__device__ __half g_w1th[(size_t)128 * 256];           // w1^T hi [n][k]
__device__ __half g_w1tl[(size_t)128 * 256];           // w1^T lo
__device__ __half g_ahalf[(size_t)4096 * 40];          // a = x@wq1 (fp16)
__device__ __half g_b[(size_t)4096 * 40];              // b = silu(x@wk1)
__device__ __half g_ct[(size_t)4 * 40 * 1024];         // c^T  [b][40][n]
__device__ __half g_gt[(size_t)64 * 1600];             // G^T per (h,hp)
__device__ __half g_wv2t[(size_t)8 * 64 * 40];         // wv2^T per head [h][d][40]
__device__ __half g_attn16[(size_t)4096 * 512];        // attention out (fp16)
__device__ __half g_woT[(size_t)256 * 512];            // wo^T fp16 [n][k]

__device__ __forceinline__ float ex2f(float x) {
    float y;
    asm("ex2.approx.ftz.f32 %0, %1;" : "=f"(y) : "f"(x));
    return y;
}

__device__ __forceinline__ unsigned ex2h2(float a, float b) {
    __half2 h = __floats2half2_rn(a, b);
    unsigned u = *reinterpret_cast<unsigned*>(&h);
    unsigned r;
    asm("ex2.approx.f16x2 %0, %1;" : "=r"(r) : "r"(u));
    return r;
}

__device__ __forceinline__ unsigned packh2(float a, float b) {
    __half2 h = __floats2half2_rn(a, b);
    return *reinterpret_cast<unsigned*>(&h);
}

__device__ __forceinline__ void mma16816(float (&c)[4], const unsigned (&a)[4],
                                         unsigned b0, unsigned b1) {
    asm volatile(
        "mma.sync.aligned.m16n8k16.row.col.f32.f16.f16.f32 "
        "{%0,%1,%2,%3}, {%4,%5,%6,%7}, {%8,%9}, {%0,%1,%2,%3};\n"
        : "+f"(c[0]), "+f"(c[1]), "+f"(c[2]), "+f"(c[3])
        : "r"(a[0]), "r"(a[1]), "r"(a[2]), "r"(a[3]), "r"(b0), "r"(b1));
}

__device__ __forceinline__ void mma16808(float (&c)[4], unsigned a0, unsigned a1,
                                         unsigned b0) {
    asm volatile(
        "mma.sync.aligned.m16n8k8.row.col.f32.f16.f16.f32 "
        "{%0,%1,%2,%3}, {%4,%5}, {%6}, {%0,%1,%2,%3};\n"
        : "+f"(c[0]), "+f"(c[1]), "+f"(c[2]), "+f"(c[3])
        : "r"(a0), "r"(a1), "r"(b0));
}

__device__ __forceinline__ void cp16(void* s, const void* g) {
    unsigned sa = (unsigned)__cvta_generic_to_shared(s);
    asm volatile("cp.async.cg.shared.global [%0], [%1], 16;\n" :: "r"(sa), "l"(g));
}

__device__ __forceinline__ void ldsm_x4(unsigned& r0, unsigned& r1, unsigned& r2,
                                        unsigned& r3, const void* p) {
    unsigned a = (unsigned)__cvta_generic_to_shared(p);
    asm volatile("ldmatrix.sync.aligned.m8n8.x4.shared.b16 {%0,%1,%2,%3}, [%4];"
                 : "=r"(r0), "=r"(r1), "=r"(r2), "=r"(r3) : "r"(a));
}

// split fp32 -> (hi, lo) packed fragments
__device__ __forceinline__ void split2(float a, float b, unsigned& hi, unsigned& lo) {
    __half h0 = __float2half_rn(a), h1 = __float2half_rn(b);
    __half2 hh = __halves2half2(h0, h1);
    hi = *reinterpret_cast<unsigned*>(&hh);
    __half2 ll = __floats2half2_rn(a - __half2float(h0), b - __half2float(h1));
    lo = *reinterpret_cast<unsigned*>(&ll);
}

// ---------------------------------------------------------------------------
// pre_kernel v4 (unchanged)
// ---------------------------------------------------------------------------
__global__ __launch_bounds__(256) void pre_kernel(
    const float* __restrict__ wq1, const float* __restrict__ wk1,
    const float* __restrict__ wv1,
    const float* __restrict__ wq2, const float* __restrict__ wk2,
    const float* __restrict__ wv2, const float* __restrict__ wo) {
    __shared__ float sf[5200];

    const int bx = blockIdx.x;
    const int tid = threadIdx.x;

    if (bx < 64) {
        float (*sQ)[65] = reinterpret_cast<float (*)[65]>(sf);
        float (*sK)[65] = reinterpret_cast<float (*)[65]>(sf + 2600);
        const int h = bx >> 3, hp = bx & 7;
        for (int idx = tid; idx < 2560; idx += 256) {
            int k = idx >> 6, d = idx & 63;
            sQ[k][d] = wq2[(size_t)k * 512 + h * 64 + d];
            sK[k][d] = wk2[(size_t)k * 512 + hp * 64 + d];
        }
        __syncthreads();
        const float SCALE = 0.125f * 1.4426950408889634f;
        for (int idx = tid; idx < 1600; idx += 256) {
            int c = idx / 40, k = idx % 40;
            float s = 0.f;
#pragma unroll 8
            for (int d = 0; d < 64; d++) s += sQ[k][d] * sK[c][d];
            g_gt[(size_t)bx * 1600 + c * 40 + k] = __float2half_rn(s * SCALE);
        }
    } else if (bx < 72) {
        float (*sT)[65] = reinterpret_cast<float (*)[65]>(sf);
        const int h = bx - 64;
        for (int idx = tid; idx < 2560; idx += 256) {
            int k = idx >> 6, d = idx & 63;
            sT[k][d] = wv2[(size_t)k * 512 + h * 64 + d];
        }
        __syncthreads();
        for (int idx = tid; idx < 2560; idx += 256) {
            int d = idx / 40, k = idx % 40;
            g_wv2t[(size_t)h * 2560 + idx] = __float2half_rn(sT[k][d]);
        }
    } else if (bx < 104) {
        float (*sT)[65] = reinterpret_cast<float (*)[65]>(sf);
        const int blk = bx - 72;
        const int k0 = (blk & 7) * 64, n0 = (blk >> 3) * 64;
#pragma unroll
        for (int i = 0; i < 16; i++) {
            int idx = i * 256 + tid;
            int r = idx >> 6, c = idx & 63;
            sT[r][c] = wo[(size_t)(k0 + r) * 256 + n0 + c];
        }
        __syncthreads();
#pragma unroll
        for (int i = 0; i < 16; i++) {
            int idx = i * 256 + tid;
            int rn = idx >> 6, ck = idx & 63;
            g_woT[(size_t)(n0 + rn) * 512 + k0 + ck] = __float2half_rn(sT[ck][rn]);
        }
    } else {
        const int base = (bx - 104) * 15360;
        for (int i = tid; i < 15360; i += 256) {
            int e = base + i;
            int n = e >> 8, k = e & 255;
            int proj = n / 40, c = n % 40;
            const float* w1 = (proj == 0) ? wq1 : (proj == 1 ? wk1 : wv1);
            float v = w1[(size_t)k * 40 + c];
            __half hh = __float2half_rn(v);
            g_w1th[(size_t)n * 256 + k] = hh;
            g_w1tl[(size_t)n * 256 + k] = __float2half_rn(v - __half2float(hh));
        }
    }
}

// ---------------------------------------------------------------------------
// proj_mma v2 (unchanged)
// ---------------------------------------------------------------------------
__global__ __launch_bounds__(128) void proj_mma(const float* __restrict__ x) {
    const int tid = threadIdx.x;
    const int w = tid >> 5, lane = tid & 31;
    const int gi = lane >> 2, tig = lane & 3;
    const int row0 = blockIdx.x * 32 + (w & 1) * 16;
    const int n0 = (w >> 1) * 64;

    const float* x0 = x + (size_t)(row0 + gi) * 256;
    const float* x8 = x0 + 8 * 256;

    float acc[8][4];
#pragma unroll
    for (int nt = 0; nt < 8; nt++)
#pragma unroll
        for (int q = 0; q < 4; q++) acc[nt][q] = 0.f;

#pragma unroll
    for (int k = 0; k < 16; k++) {
        const int kc = k * 16 + tig * 2;
        unsigned ah[4], al[4];
        float2 v;
        v = *reinterpret_cast<const float2*>(x0 + kc);     split2(v.x, v.y, ah[0], al[0]);
        v = *reinterpret_cast<const float2*>(x8 + kc);     split2(v.x, v.y, ah[1], al[1]);
        v = *reinterpret_cast<const float2*>(x0 + kc + 8); split2(v.x, v.y, ah[2], al[2]);
        v = *reinterpret_cast<const float2*>(x8 + kc + 8); split2(v.x, v.y, ah[3], al[3]);

#pragma unroll
        for (int nt = 0; nt < 8; nt++) {
            const size_t wrow = (size_t)(n0 + nt * 8 + gi) * 256 + k * 16 + tig * 2;
            unsigned b0h = *reinterpret_cast<const unsigned*>(g_w1th + wrow);
            unsigned b1h = *reinterpret_cast<const unsigned*>(g_w1th + wrow + 8);
            unsigned b0l = *reinterpret_cast<const unsigned*>(g_w1tl + wrow);
            unsigned b1l = *reinterpret_cast<const unsigned*>(g_w1tl + wrow + 8);
            mma16816(acc[nt], ah, b0h, b1h);
            mma16816(acc[nt], al, b0h, b1h);
            mma16816(acc[nt], ah, b0l, b1l);
        }
    }

#pragma unroll
    for (int nt = 0; nt < 8; nt++) {
        const int col = n0 + nt * 8 + tig * 2;
        if (col >= 120) continue;
        const int proj = col / 40, c = col % 40;
#pragma unroll
        for (int half = 0; half < 2; half++) {
            const int r = row0 + gi + half * 8;
            float v0 = acc[nt][2 * half], v1 = acc[nt][2 * half + 1];
            if (proj == 0) {
                *reinterpret_cast<unsigned*>(g_ahalf + (size_t)r * 40 + c) =
                    packh2(v0, v1);
            } else if (proj == 1) {
                v0 = v0 / (1.0f + __expf(-v0));
                v1 = v1 / (1.0f + __expf(-v1));
                *reinterpret_cast<unsigned*>(g_b + (size_t)r * 40 + c) =
                    packh2(v0, v1);
            } else {
                const int bb = r >> 10, n = r & 1023;
                g_ct[((size_t)bb * 40 + c) * 1024 + n]     = __float2half_rn(v0);
                g_ct[((size_t)bb * 40 + c + 1) * 1024 + n] = __float2half_rn(v1);
            }
        }
    }
}

// ---------------------------------------------------------------------------
// Flash attention v6: tree row-max + packed half2 shfl-max (M rounded down to
// fp16 — consistent M everywhere, so math stays exact). Rest identical to v5.
// ---------------------------------------------------------------------------
#define CTS   72
#define CT_BUFSZ (41 * CTS)
#define CT_REGION (4 * CT_BUFSZ + 7 * CTS)
#define WVSZ  2560
#define B_HALVES 40960
#define ATTN_SMEM ((B_HALVES + CT_REGION + WVSZ) * 2)

__global__ __launch_bounds__(256, 2) void attn_kernel() {
    extern __shared__ __half sm[];
    __half* b_s  = sm;
    __half* ct_s = sm + B_HALVES;
    __half* wv_s = sm + B_HALVES + CT_REGION;

    const int b = blockIdx.y;
    const int qt = blockIdx.x;
    const int h = qt >> 3;
    const int n0 = (qt & 7) * 128;
    const int tid = threadIdx.x;
    const int w = tid >> 5, lane = tid & 31;
    const int gi = lane >> 2, tig = lane & 3;
    const int l8 = lane & 7, mrow = lane >> 3;
    const int r8 = (lane >> 3) * 8 + (lane & 7);

    const __half* gb = g_b + (size_t)b * 1024 * 40;
    const __half* gct = g_ct + (size_t)b * 40 * 1024;

    for (int idx = tid; idx < 5120; idx += 256)
        cp16(&b_s[idx * 8], gb + idx * 8);
#pragma unroll
    for (int pf = 0; pf < 2; pf++) {
        __half* dc = ct_s + pf * CT_BUFSZ;
        for (int idx = tid; idx < 320; idx += 256) {
            int row = idx >> 3, seg = idx & 7;
            cp16(&dc[row * CTS + seg * 8], gct + (size_t)row * 1024 + pf * 64 + seg * 8);
        }
    }
    for (int idx = tid; idx < 320; idx += 256)
        cp16(&wv_s[idx * 8], g_wv2t + idx * 8);
    asm volatile("cp.async.commit_group;\n");
    asm volatile("cp.async.wait_group 0;\n");
    if (tid < 128) {
        int bufi = tid >> 5, seg = tid & 31;
        *reinterpret_cast<unsigned*>(&ct_s[bufi * CT_BUFSZ + 40 * CTS + seg * 2]) =
            0x3C003C00u;
    }
    __syncthreads();

    float m[2] = {-1e30f, -1e30f}, l[2] = {0.f, 0.f};
    float O[8][4], T[6][4];
#pragma unroll
    for (int dt = 0; dt < 8; dt++)
#pragma unroll
        for (int q = 0; q < 4; q++) O[dt][q] = 0.f;
#pragma unroll
    for (int n = 0; n < 6; n++)
#pragma unroll
        for (int q = 0; q < 4; q++) T[n][q] = 0.f;

    unsigned qf[2][4], qf8[2];
    const __half* ar0 = g_ahalf + (size_t)(((b << 10) | n0) + w * 16 + gi) * 40;
    const __half* ar1 = ar0 + 8 * 40;

    for (int tt = 0; tt < 128; tt += 2) {
        const int hp = tt >> 4;

        asm volatile("cp.async.wait_group 0;\n");
        __syncthreads();

        if (tt + 2 < 128) {
#pragma unroll
            for (int pf = 0; pf < 2; pf++) {
                int ntile = tt + 2 + pf;
                int key0 = (ntile & 15) * 64;
                __half* dc = ct_s + (ntile & 3) * CT_BUFSZ;
                for (int idx = tid; idx < 320; idx += 256) {
                    int row = idx >> 3, seg = idx & 7;
                    cp16(&dc[row * CTS + seg * 8],
                         gct + (size_t)row * 1024 + key0 + seg * 8);
                }
            }
        }
        if ((tt & 15) == 0 && tt > 0) {
            const __half* gw = g_wv2t + (size_t)hp * 2560;
            for (int idx = tid; idx < 320; idx += 256)
                cp16(&wv_s[idx * 8], gw + idx * 8);
        }
        asm volatile("cp.async.commit_group;\n");

        if ((tt & 15) == 0) {
            unsigned af[2][4], af8[2];
#pragma unroll
            for (int kc = 0; kc < 2; kc++) {
                int cc = kc * 16 + tig * 2;
                af[kc][0] = *reinterpret_cast<const unsigned*>(ar0 + cc);
                af[kc][1] = *reinterpret_cast<const unsigned*>(ar1 + cc);
                af[kc][2] = *reinterpret_cast<const unsigned*>(ar0 + cc + 8);
                af[kc][3] = *reinterpret_cast<const unsigned*>(ar1 + cc + 8);
            }
            af8[0] = *reinterpret_cast<const unsigned*>(ar0 + 32 + tig * 2);
            af8[1] = *reinterpret_cast<const unsigned*>(ar1 + 32 + tig * 2);

            const __half* gg = g_gt + (size_t)(h * 8 + hp) * 1600;
            float tq[5][4];
#pragma unroll
            for (int nt = 0; nt < 5; nt++) {
                const __half* gr = gg + (nt * 8 + gi) * 40 + tig * 2;
                unsigned g0 = *reinterpret_cast<const unsigned*>(gr);
                unsigned g1 = *reinterpret_cast<const unsigned*>(gr + 8);
                unsigned g2 = *reinterpret_cast<const unsigned*>(gr + 16);
                unsigned g3 = *reinterpret_cast<const unsigned*>(gr + 24);
                unsigned g4 = *reinterpret_cast<const unsigned*>(gr + 32);
                tq[nt][0] = tq[nt][1] = tq[nt][2] = tq[nt][3] = 0.f;
                mma16816(tq[nt], af[0], g0, g1);
                mma16816(tq[nt], af[1], g2, g3);
                mma16808(tq[nt], af8[0], af8[1], g4);
            }
#pragma unroll
            for (int kc = 0; kc < 2; kc++) {
                qf[kc][0] = packh2(tq[2 * kc][0],     tq[2 * kc][1]);
                qf[kc][1] = packh2(tq[2 * kc][2],     tq[2 * kc][3]);
                qf[kc][2] = packh2(tq[2 * kc + 1][0], tq[2 * kc + 1][1]);
                qf[kc][3] = packh2(tq[2 * kc + 1][2], tq[2 * kc + 1][3]);
            }
            qf8[0] = packh2(tq[4][0], tq[4][1]);
            qf8[1] = packh2(tq[4][2], tq[4][3]);
        }

#pragma unroll
        for (int sub = 0; sub < 2; sub++) {
            const int tile = tt + sub;
            const int t = tile & 15;
            const __half* ct_t = ct_s + (tile & 3) * CT_BUFSZ;

            unsigned kb8v[8];
            ldsm_x4(kb8v[0], kb8v[1], kb8v[2], kb8v[3],
                    &b_s[(t * 64 + r8) * 40 + 32]);
            ldsm_x4(kb8v[4], kb8v[5], kb8v[6], kb8v[7],
                    &b_s[(t * 64 + 32 + r8) * 40 + 32]);

            float S[8][4];
#pragma unroll
            for (int nt = 0; nt < 8; nt++)
#pragma unroll
                for (int q = 0; q < 4; q++) S[nt][q] = 0.f;

#pragma unroll
            for (int nt = 0; nt < 8; nt++) {
                unsigned kb0[2], kb1[2];
                ldsm_x4(kb0[0], kb1[0], kb0[1], kb1[1],
                        &b_s[(t * 64 + nt * 8 + l8) * 40 + mrow * 8]);
                mma16816(S[nt], qf[0], kb0[0], kb1[0]);
                mma16816(S[nt], qf[1], kb0[1], kb1[1]);
                mma16808(S[nt], qf8[0], qf8[1], kb8v[nt]);
            }

            // ---- row max: pairwise tree (depth 4) per h2, then packed
            //      half2 shfl reduce across the quad. M rounded DOWN to fp16;
            //      same M used everywhere so math stays exact. ----
            {
                float tmax[2];
#pragma unroll
                for (int h2 = 0; h2 < 2; h2++) {
                    float a0 = fmaxf(S[0][2 * h2], S[0][2 * h2 + 1]);
                    float a1 = fmaxf(S[1][2 * h2], S[1][2 * h2 + 1]);
                    float a2 = fmaxf(S[2][2 * h2], S[2][2 * h2 + 1]);
                    float a3 = fmaxf(S[3][2 * h2], S[3][2 * h2 + 1]);
                    float a4 = fmaxf(S[4][2 * h2], S[4][2 * h2 + 1]);
                    float a5 = fmaxf(S[5][2 * h2], S[5][2 * h2 + 1]);
                    float a6 = fmaxf(S[6][2 * h2], S[6][2 * h2 + 1]);
                    float a7 = fmaxf(S[7][2 * h2], S[7][2 * h2 + 1]);
                    float b0 = fmaxf(a0, a1), b1 = fmaxf(a2, a3);
                    float b2 = fmaxf(a4, a5), b3 = fmaxf(a6, a7);
                    tmax[h2] = fmaxf(fmaxf(b0, b1), fmaxf(b2, b3));
                }
                __half2 th = __halves2half2(__float2half_rd(tmax[0]),
                                            __float2half_rd(tmax[1]));
                unsigned tu = *reinterpret_cast<unsigned*>(&th);
                unsigned o1 = __shfl_xor_sync(0xffffffffu, tu, 1);
                th = __hmax2(th, *reinterpret_cast<__half2*>(&o1));
                tu = *reinterpret_cast<unsigned*>(&th);
                unsigned o2 = __shfl_xor_sync(0xffffffffu, tu, 2);
                th = __hmax2(th, *reinterpret_cast<__half2*>(&o2));
                float2 tf = __half22float2(th);
                float tmv[2] = {tf.x, tf.y};
#pragma unroll
                for (int h2 = 0; h2 < 2; h2++) {
                    if (tmv[h2] > m[h2]) {
                        float al = ex2f(m[h2] - tmv[h2]);
                        m[h2] = tmv[h2];
                        l[h2] *= al;
#pragma unroll
                        for (int dt = 0; dt < 8; dt++) {
                            O[dt][2 * h2] *= al;
                            O[dt][2 * h2 + 1] *= al;
                        }
#pragma unroll
                        for (int n = 0; n < 6; n++) {
                            T[n][2 * h2] *= al;
                            T[n][2 * h2 + 1] *= al;
                        }
                    }
                }
            }

            unsigned pa[4][4];
#pragma unroll
            for (int nt = 0; nt < 8; nt++) {
                unsigned p01 = ex2h2(S[nt][0] - m[0], S[nt][1] - m[0]);
                unsigned p23 = ex2h2(S[nt][2] - m[1], S[nt][3] - m[1]);
                pa[nt >> 1][(nt & 1) * 2]     = p01;
                pa[nt >> 1][(nt & 1) * 2 + 1] = p23;
            }

#pragma unroll
            for (int n = 0; n < 6; n++) {
                unsigned vb0[4], vb1[4];
                const __half* va = &ct_t[(n * 8 + l8) * CTS + mrow * 8];
                ldsm_x4(vb0[0], vb1[0], vb0[1], vb1[1], va);
                ldsm_x4(vb0[2], vb1[2], vb0[3], vb1[3], va + 32);
#pragma unroll
                for (int kc = 0; kc < 4; kc++)
                    mma16816(T[n], pa[kc], vb0[kc], vb1[kc]);
            }

            if (t == 15) {
                unsigned at16[2][4], at8a, at8b;
#pragma unroll
                for (int kc = 0; kc < 2; kc++) {
                    at16[kc][0] = packh2(T[2 * kc][0],     T[2 * kc][1]);
                    at16[kc][1] = packh2(T[2 * kc][2],     T[2 * kc][3]);
                    at16[kc][2] = packh2(T[2 * kc + 1][0], T[2 * kc + 1][1]);
                    at16[kc][3] = packh2(T[2 * kc + 1][2], T[2 * kc + 1][3]);
                }
                at8a = packh2(T[4][0], T[4][1]);
                at8b = packh2(T[4][2], T[4][3]);

                unsigned wb8v[8];
                ldsm_x4(wb8v[0], wb8v[1], wb8v[2], wb8v[3],
                        &wv_s[r8 * 40 + 32]);
                ldsm_x4(wb8v[4], wb8v[5], wb8v[6], wb8v[7],
                        &wv_s[(32 + r8) * 40 + 32]);

#pragma unroll
                for (int dt = 0; dt < 8; dt++) {
                    unsigned wb0[2], wb1[2];
                    ldsm_x4(wb0[0], wb1[0], wb0[1], wb1[1],
                            &wv_s[(dt * 8 + l8) * 40 + mrow * 8]);
                    mma16816(O[dt], at16[0], wb0[0], wb1[0]);
                    mma16816(O[dt], at16[1], wb0[1], wb1[1]);
                    mma16808(O[dt], at8a, at8b, wb8v[dt]);
                }
                if (tig == 0) {
                    l[0] += T[5][0];
                    l[1] += T[5][2];
                }
#pragma unroll
                for (int n = 0; n < 6; n++)
#pragma unroll
                    for (int q = 0; q < 4; q++) T[n][q] = 0.f;
            }
        }
    }

#pragma unroll
    for (int h2 = 0; h2 < 2; h2++) {
        float lt = __shfl_sync(0xffffffffu, l[h2], lane & 28);
        float inv = 1.0f / lt;
        int n = n0 + w * 16 + gi + h2 * 8;
        __half* orow = g_attn16 + ((size_t)((b << 10) | n)) * 512 + h * 64;
#pragma unroll
        for (int dt = 0; dt < 8; dt++) {
            *reinterpret_cast<unsigned*>(orow + dt * 8 + tig * 2) =
                packh2(O[dt][2 * h2] * inv, O[dt][2 * h2 + 1] * inv);
        }
    }
}

// ---------------------------------------------------------------------------
// out_gemm (reverted to best-measured R11 shape: 64x64, 2-buffer pipeline)
// ---------------------------------------------------------------------------
__global__ __launch_bounds__(128) void out_gemm(
    const float* __restrict__ bo, float* __restrict__ out) {
    __shared__ __half sA2[2][64 * 72];
    __shared__ __half sB2[2][64 * 72];

    const int bm0 = blockIdx.x * 64;
    const int bn0 = blockIdx.y * 64;
    const int tid = threadIdx.x;
    const int w = tid >> 5, lane = tid & 31;
    const int gi = lane >> 2, tig = lane & 3;
    const int l8 = lane & 7, mrow = lane >> 3;

    float acc[8][4];
#pragma unroll
    for (int nt = 0; nt < 8; nt++)
#pragma unroll
        for (int q = 0; q < 4; q++) acc[nt][q] = 0.f;

    const int ar = (lane & 15);
    const int ac = (lane >> 4) * 8;

#pragma unroll
    for (int i = 0; i < 4; i++) {
        int idx = tid + i * 128;
        int r = idx >> 3, s = idx & 7;
        cp16(&sA2[0][r * 72 + s * 8], g_attn16 + (size_t)(bm0 + r) * 512 + s * 8);
        cp16(&sB2[0][r * 72 + s * 8], g_woT + (size_t)(bn0 + r) * 512 + s * 8);
    }
    asm volatile("cp.async.commit_group;\n");

    for (int kc = 0; kc < 8; kc++) {
        const int buf = kc & 1;
        if (kc + 1 < 8) {
#pragma unroll
            for (int i = 0; i < 4; i++) {
                int idx = tid + i * 128;
                int r = idx >> 3, s = idx & 7;
                cp16(&sA2[buf ^ 1][r * 72 + s * 8],
                     g_attn16 + (size_t)(bm0 + r) * 512 + (kc + 1) * 64 + s * 8);
                cp16(&sB2[buf ^ 1][r * 72 + s * 8],
                     g_woT + (size_t)(bn0 + r) * 512 + (kc + 1) * 64 + s * 8);
            }
            asm volatile("cp.async.commit_group;\n");
            asm volatile("cp.async.wait_group 1;\n");
        } else {
            asm volatile("cp.async.wait_group 0;\n");
        }
        __syncthreads();

        const int m0 = w * 16;
#pragma unroll
        for (int ksp = 0; ksp < 2; ksp++) {
            unsigned af0[4], af1[4];
            ldsm_x4(af0[0], af0[1], af0[2], af0[3],
                    &sA2[buf][(m0 + ar) * 72 + ksp * 32 + ac]);
            ldsm_x4(af1[0], af1[1], af1[2], af1[3],
                    &sA2[buf][(m0 + ar) * 72 + ksp * 32 + 16 + ac]);
#pragma unroll
            for (int nt = 0; nt < 8; nt++) {
                unsigned b0a, b1a, b0b, b1b;
                ldsm_x4(b0a, b1a, b0b, b1b,
                        &sB2[buf][(nt * 8 + l8) * 72 + ksp * 32 + mrow * 8]);
                mma16816(acc[nt], af0, b0a, b1a);
                mma16816(acc[nt], af1, b0b, b1b);
            }
        }
        __syncthreads();
    }

    const int r0 = bm0 + w * 16 + gi;
#pragma unroll
    for (int nt = 0; nt < 8; nt++) {
        int col = bn0 + nt * 8 + tig * 2;
        float b0 = bo[col], b1 = bo[col + 1];
        float2 o0 = make_float2(acc[nt][0] + b0, acc[nt][1] + b1);
        float2 o1 = make_float2(acc[nt][2] + b0, acc[nt][3] + b1);
        *reinterpret_cast<float2*>(out + (size_t)r0 * 256 + col) = o0;
        *reinterpret_cast<float2*>(out + (size_t)(r0 + 8) * 256 + col) = o1;
    }
}

// ---------------------------------------------------------------------------
extern "C" void kernel_launch(void* const* d_in, const int* in_sizes, int n_in,
                              void* d_out, int out_size) {
    const float* x   = (const float*)d_in[0];
    const float* wq1 = (const float*)d_in[1];
    const float* wq2 = (const float*)d_in[2];
    const float* wk1 = (const float*)d_in[3];
    const float* wk2 = (const float*)d_in[4];
    const float* wv1 = (const float*)d_in[5];
    const float* wv2 = (const float*)d_in[6];
    const float* wo  = (const float*)d_in[7];
    const float* bo  = (const float*)d_in[8];
    float* out = (float*)d_out;

    cudaFuncSetAttribute(attn_kernel, cudaFuncAttributeMaxDynamicSharedMemorySize,
                         ATTN_SMEM);

    pre_kernel<<<106, 256>>>(wq1, wk1, wv1, wq2, wk2, wv2, wo);
    proj_mma<<<128, 128>>>(x);
    attn_kernel<<<dim3(64, 4), 256, ATTN_SMEM>>>();
    out_gemm<<<dim3(64, 4), 128>>>(bo, out);
}

// round 15
// speedup vs baseline: 1.0236x; 1.0236x over previous
#include <cuda_runtime.h>
#include <cuda_fp16.h>
#include <cstdint>

#define NN    1024
#define QSZ   256
#define BOT   40

// ------------------------- scratch (no allocs allowed) -----------------------
__device__ __half g_w1th[(size_t)128 * 256];           // w1^T hi [n][k]
__device__ __half g_w1tl[(size_t)128 * 256];           // w1^T lo
__device__ __half g_ahalf[(size_t)4096 * 40];          // a = x@wq1 (fp16)
__device__ __half g_b[(size_t)4096 * 40];              // b = silu(x@wk1)
__device__ __half g_ct[(size_t)4 * 40 * 1024];         // c^T  [b][40][n]
__device__ __half g_gt[(size_t)64 * 1600];             // G^T per (h,hp)
__device__ __half g_wv2t[(size_t)8 * 64 * 40];         // wv2^T per head [h][d][40]
__device__ __half g_attn16[(size_t)4096 * 512];        // attention out (fp16)
__device__ __half g_woT[(size_t)256 * 512];            // wo^T fp16 [n][k]

__device__ __forceinline__ float ex2f(float x) {
    float y;
    asm("ex2.approx.ftz.f32 %0, %1;" : "=f"(y) : "f"(x));
    return y;
}

__device__ __forceinline__ unsigned ex2h2(float a, float b) {
    __half2 h = __floats2half2_rn(a, b);
    unsigned u = *reinterpret_cast<unsigned*>(&h);
    unsigned r;
    asm("ex2.approx.f16x2 %0, %1;" : "=r"(r) : "r"(u));
    return r;
}

__device__ __forceinline__ unsigned packh2(float a, float b) {
    __half2 h = __floats2half2_rn(a, b);
    return *reinterpret_cast<unsigned*>(&h);
}

__device__ __forceinline__ void mma16816(float (&c)[4], const unsigned (&a)[4],
                                         unsigned b0, unsigned b1) {
    asm volatile(
        "mma.sync.aligned.m16n8k16.row.col.f32.f16.f16.f32 "
        "{%0,%1,%2,%3}, {%4,%5,%6,%7}, {%8,%9}, {%0,%1,%2,%3};\n"
        : "+f"(c[0]), "+f"(c[1]), "+f"(c[2]), "+f"(c[3])
        : "r"(a[0]), "r"(a[1]), "r"(a[2]), "r"(a[3]), "r"(b0), "r"(b1));
}

__device__ __forceinline__ void mma16808(float (&c)[4], unsigned a0, unsigned a1,
                                         unsigned b0) {
    asm volatile(
        "mma.sync.aligned.m16n8k8.row.col.f32.f16.f16.f32 "
        "{%0,%1,%2,%3}, {%4,%5}, {%6}, {%0,%1,%2,%3};\n"
        : "+f"(c[0]), "+f"(c[1]), "+f"(c[2]), "+f"(c[3])
        : "r"(a0), "r"(a1), "r"(b0));
}

__device__ __forceinline__ void cp16(void* s, const void* g) {
    unsigned sa = (unsigned)__cvta_generic_to_shared(s);
    asm volatile("cp.async.cg.shared.global [%0], [%1], 16;\n" :: "r"(sa), "l"(g));
}

__device__ __forceinline__ void ldsm_x4(unsigned& r0, unsigned& r1, unsigned& r2,
                                        unsigned& r3, const void* p) {
    unsigned a = (unsigned)__cvta_generic_to_shared(p);
    asm volatile("ldmatrix.sync.aligned.m8n8.x4.shared.b16 {%0,%1,%2,%3}, [%4];"
                 : "=r"(r0), "=r"(r1), "=r"(r2), "=r"(r3) : "r"(a));
}

// split fp32 -> (hi, lo) packed fragments
__device__ __forceinline__ void split2(float a, float b, unsigned& hi, unsigned& lo) {
    __half h0 = __float2half_rn(a), h1 = __float2half_rn(b);
    __half2 hh = __halves2half2(h0, h1);
    hi = *reinterpret_cast<unsigned*>(&hh);
    __half2 ll = __floats2half2_rn(a - __half2float(h0), b - __half2float(h1));
    lo = *reinterpret_cast<unsigned*>(&ll);
}

// ---------------------------------------------------------------------------
// pre_kernel v4: gmat (0..63) + wv2t transpose (64..71) + wo transpose
// (72..103) + w1t hi/lo (104..105). grid 106.
// ---------------------------------------------------------------------------
__global__ __launch_bounds__(256) void pre_kernel(
    const float* __restrict__ wq1, const float* __restrict__ wk1,
    const float* __restrict__ wv1,
    const float* __restrict__ wq2, const float* __restrict__ wk2,
    const float* __restrict__ wv2, const float* __restrict__ wo) {
    __shared__ float sf[5200];

    const int bx = blockIdx.x;
    const int tid = threadIdx.x;

    if (bx < 64) {
        float (*sQ)[65] = reinterpret_cast<float (*)[65]>(sf);
        float (*sK)[65] = reinterpret_cast<float (*)[65]>(sf + 2600);
        const int h = bx >> 3, hp = bx & 7;
        for (int idx = tid; idx < 2560; idx += 256) {
            int k = idx >> 6, d = idx & 63;
            sQ[k][d] = wq2[(size_t)k * 512 + h * 64 + d];
            sK[k][d] = wk2[(size_t)k * 512 + hp * 64 + d];
        }
        __syncthreads();
        const float SCALE = 0.125f * 1.4426950408889634f;
        for (int idx = tid; idx < 1600; idx += 256) {
            int c = idx / 40, k = idx % 40;
            float s = 0.f;
#pragma unroll 8
            for (int d = 0; d < 64; d++) s += sQ[k][d] * sK[c][d];
            g_gt[(size_t)bx * 1600 + c * 40 + k] = __float2half_rn(s * SCALE);
        }
    } else if (bx < 72) {
        float (*sT)[65] = reinterpret_cast<float (*)[65]>(sf);
        const int h = bx - 64;
        for (int idx = tid; idx < 2560; idx += 256) {
            int k = idx >> 6, d = idx & 63;
            sT[k][d] = wv2[(size_t)k * 512 + h * 64 + d];
        }
        __syncthreads();
        for (int idx = tid; idx < 2560; idx += 256) {
            int d = idx / 40, k = idx % 40;
            g_wv2t[(size_t)h * 2560 + idx] = __float2half_rn(sT[k][d]);
        }
    } else if (bx < 104) {
        float (*sT)[65] = reinterpret_cast<float (*)[65]>(sf);
        const int blk = bx - 72;
        const int k0 = (blk & 7) * 64, n0 = (blk >> 3) * 64;
#pragma unroll
        for (int i = 0; i < 16; i++) {
            int idx = i * 256 + tid;
            int r = idx >> 6, c = idx & 63;
            sT[r][c] = wo[(size_t)(k0 + r) * 256 + n0 + c];
        }
        __syncthreads();
#pragma unroll
        for (int i = 0; i < 16; i++) {
            int idx = i * 256 + tid;
            int rn = idx >> 6, ck = idx & 63;
            g_woT[(size_t)(n0 + rn) * 512 + k0 + ck] = __float2half_rn(sT[ck][rn]);
        }
    } else {
        const int base = (bx - 104) * 15360;
        for (int i = tid; i < 15360; i += 256) {
            int e = base + i;
            int n = e >> 8, k = e & 255;
            int proj = n / 40, c = n % 40;
            const float* w1 = (proj == 0) ? wq1 : (proj == 1 ? wk1 : wv1);
            float v = w1[(size_t)k * 40 + c];
            __half hh = __float2half_rn(v);
            g_w1th[(size_t)n * 256 + k] = hh;
            g_w1tl[(size_t)n * 256 + k] = __float2half_rn(v - __half2float(hh));
        }
    }
}

// ---------------------------------------------------------------------------
// proj_mma v2: x read fp32 directly, split to hi/lo fragments in registers.
// ---------------------------------------------------------------------------
__global__ __launch_bounds__(128) void proj_mma(const float* __restrict__ x) {
    const int tid = threadIdx.x;
    const int w = tid >> 5, lane = tid & 31;
    const int gi = lane >> 2, tig = lane & 3;
    const int row0 = blockIdx.x * 32 + (w & 1) * 16;
    const int n0 = (w >> 1) * 64;

    const float* x0 = x + (size_t)(row0 + gi) * 256;
    const float* x8 = x0 + 8 * 256;

    float acc[8][4];
#pragma unroll
    for (int nt = 0; nt < 8; nt++)
#pragma unroll
        for (int q = 0; q < 4; q++) acc[nt][q] = 0.f;

#pragma unroll
    for (int k = 0; k < 16; k++) {
        const int kc = k * 16 + tig * 2;
        unsigned ah[4], al[4];
        float2 v;
        v = *reinterpret_cast<const float2*>(x0 + kc);     split2(v.x, v.y, ah[0], al[0]);
        v = *reinterpret_cast<const float2*>(x8 + kc);     split2(v.x, v.y, ah[1], al[1]);
        v = *reinterpret_cast<const float2*>(x0 + kc + 8); split2(v.x, v.y, ah[2], al[2]);
        v = *reinterpret_cast<const float2*>(x8 + kc + 8); split2(v.x, v.y, ah[3], al[3]);

#pragma unroll
        for (int nt = 0; nt < 8; nt++) {
            const size_t wrow = (size_t)(n0 + nt * 8 + gi) * 256 + k * 16 + tig * 2;
            unsigned b0h = *reinterpret_cast<const unsigned*>(g_w1th + wrow);
            unsigned b1h = *reinterpret_cast<const unsigned*>(g_w1th + wrow + 8);
            unsigned b0l = *reinterpret_cast<const unsigned*>(g_w1tl + wrow);
            unsigned b1l = *reinterpret_cast<const unsigned*>(g_w1tl + wrow + 8);
            mma16816(acc[nt], ah, b0h, b1h);
            mma16816(acc[nt], al, b0h, b1h);
            mma16816(acc[nt], ah, b0l, b1l);
        }
    }

#pragma unroll
    for (int nt = 0; nt < 8; nt++) {
        const int col = n0 + nt * 8 + tig * 2;
        if (col >= 120) continue;
        const int proj = col / 40, c = col % 40;
#pragma unroll
        for (int half = 0; half < 2; half++) {
            const int r = row0 + gi + half * 8;
            float v0 = acc[nt][2 * half], v1 = acc[nt][2 * half + 1];
            if (proj == 0) {
                *reinterpret_cast<unsigned*>(g_ahalf + (size_t)r * 40 + c) =
                    packh2(v0, v1);
            } else if (proj == 1) {
                v0 = v0 / (1.0f + __expf(-v0));
                v1 = v1 / (1.0f + __expf(-v1));
                *reinterpret_cast<unsigned*>(g_b + (size_t)r * 40 + c) =
                    packh2(v0, v1);
            } else {
                const int bb = r >> 10, n = r & 1023;
                g_ct[((size_t)bb * 40 + c) * 1024 + n]     = __float2half_rn(v0);
                g_ct[((size_t)bb * 40 + c + 1) * 1024 + n] = __float2half_rn(v1);
            }
        }
    }
}

// ---------------------------------------------------------------------------
// Flash attention v5 (measured-best R12 config): in-kernel qf, ones-row l,
// branch rescale, 4 ct buffers, pair barriers, 2 CTAs/SM.
// ---------------------------------------------------------------------------
#define CTS   72
#define CT_BUFSZ (41 * CTS)
#define CT_REGION (4 * CT_BUFSZ + 7 * CTS)
#define WVSZ  2560
#define B_HALVES 40960
#define ATTN_SMEM ((B_HALVES + CT_REGION + WVSZ) * 2)

__global__ __launch_bounds__(256, 2) void attn_kernel() {
    extern __shared__ __half sm[];
    __half* b_s  = sm;
    __half* ct_s = sm + B_HALVES;
    __half* wv_s = sm + B_HALVES + CT_REGION;

    const int b = blockIdx.y;
    const int qt = blockIdx.x;
    const int h = qt >> 3;
    const int n0 = (qt & 7) * 128;
    const int tid = threadIdx.x;
    const int w = tid >> 5, lane = tid & 31;
    const int gi = lane >> 2, tig = lane & 3;
    const int l8 = lane & 7, mrow = lane >> 3;
    const int r8 = (lane >> 3) * 8 + (lane & 7);

    const __half* gb = g_b + (size_t)b * 1024 * 40;
    const __half* gct = g_ct + (size_t)b * 40 * 1024;

    for (int idx = tid; idx < 5120; idx += 256)
        cp16(&b_s[idx * 8], gb + idx * 8);
#pragma unroll
    for (int pf = 0; pf < 2; pf++) {
        __half* dc = ct_s + pf * CT_BUFSZ;
        for (int idx = tid; idx < 320; idx += 256) {
            int row = idx >> 3, seg = idx & 7;
            cp16(&dc[row * CTS + seg * 8], gct + (size_t)row * 1024 + pf * 64 + seg * 8);
        }
    }
    for (int idx = tid; idx < 320; idx += 256)
        cp16(&wv_s[idx * 8], g_wv2t + idx * 8);
    asm volatile("cp.async.commit_group;\n");
    asm volatile("cp.async.wait_group 0;\n");
    if (tid < 128) {
        int bufi = tid >> 5, seg = tid & 31;
        *reinterpret_cast<unsigned*>(&ct_s[bufi * CT_BUFSZ + 40 * CTS + seg * 2]) =
            0x3C003C00u;
    }
    __syncthreads();

    float m[2] = {-1e30f, -1e30f}, l[2] = {0.f, 0.f};
    float O[8][4], T[6][4];
#pragma unroll
    for (int dt = 0; dt < 8; dt++)
#pragma unroll
        for (int q = 0; q < 4; q++) O[dt][q] = 0.f;
#pragma unroll
    for (int n = 0; n < 6; n++)
#pragma unroll
        for (int q = 0; q < 4; q++) T[n][q] = 0.f;

    unsigned qf[2][4], qf8[2];
    const __half* ar0 = g_ahalf + (size_t)(((b << 10) | n0) + w * 16 + gi) * 40;
    const __half* ar1 = ar0 + 8 * 40;

    for (int tt = 0; tt < 128; tt += 2) {
        const int hp = tt >> 4;

        asm volatile("cp.async.wait_group 0;\n");
        __syncthreads();

        if (tt + 2 < 128) {
#pragma unroll
            for (int pf = 0; pf < 2; pf++) {
                int ntile = tt + 2 + pf;
                int key0 = (ntile & 15) * 64;
                __half* dc = ct_s + (ntile & 3) * CT_BUFSZ;
                for (int idx = tid; idx < 320; idx += 256) {
                    int row = idx >> 3, seg = idx & 7;
                    cp16(&dc[row * CTS + seg * 8],
                         gct + (size_t)row * 1024 + key0 + seg * 8);
                }
            }
        }
        if ((tt & 15) == 0 && tt > 0) {
            const __half* gw = g_wv2t + (size_t)hp * 2560;
            for (int idx = tid; idx < 320; idx += 256)
                cp16(&wv_s[idx * 8], gw + idx * 8);
        }
        asm volatile("cp.async.commit_group;\n");

        if ((tt & 15) == 0) {
            unsigned af[2][4], af8[2];
#pragma unroll
            for (int kc = 0; kc < 2; kc++) {
                int cc = kc * 16 + tig * 2;
                af[kc][0] = *reinterpret_cast<const unsigned*>(ar0 + cc);
                af[kc][1] = *reinterpret_cast<const unsigned*>(ar1 + cc);
                af[kc][2] = *reinterpret_cast<const unsigned*>(ar0 + cc + 8);
                af[kc][3] = *reinterpret_cast<const unsigned*>(ar1 + cc + 8);
            }
            af8[0] = *reinterpret_cast<const unsigned*>(ar0 + 32 + tig * 2);
            af8[1] = *reinterpret_cast<const unsigned*>(ar1 + 32 + tig * 2);

            const __half* gg = g_gt + (size_t)(h * 8 + hp) * 1600;
            float tq[5][4];
#pragma unroll
            for (int nt = 0; nt < 5; nt++) {
                const __half* gr = gg + (nt * 8 + gi) * 40 + tig * 2;
                unsigned g0 = *reinterpret_cast<const unsigned*>(gr);
                unsigned g1 = *reinterpret_cast<const unsigned*>(gr + 8);
                unsigned g2 = *reinterpret_cast<const unsigned*>(gr + 16);
                unsigned g3 = *reinterpret_cast<const unsigned*>(gr + 24);
                unsigned g4 = *reinterpret_cast<const unsigned*>(gr + 32);
                tq[nt][0] = tq[nt][1] = tq[nt][2] = tq[nt][3] = 0.f;
                mma16816(tq[nt], af[0], g0, g1);
                mma16816(tq[nt], af[1], g2, g3);
                mma16808(tq[nt], af8[0], af8[1], g4);
            }
#pragma unroll
            for (int kc = 0; kc < 2; kc++) {
                qf[kc][0] = packh2(tq[2 * kc][0],     tq[2 * kc][1]);
                qf[kc][1] = packh2(tq[2 * kc][2],     tq[2 * kc][3]);
                qf[kc][2] = packh2(tq[2 * kc + 1][0], tq[2 * kc + 1][1]);
                qf[kc][3] = packh2(tq[2 * kc + 1][2], tq[2 * kc + 1][3]);
            }
            qf8[0] = packh2(tq[4][0], tq[4][1]);
            qf8[1] = packh2(tq[4][2], tq[4][3]);
        }

#pragma unroll
        for (int sub = 0; sub < 2; sub++) {
            const int tile = tt + sub;
            const int t = tile & 15;
            const __half* ct_t = ct_s + (tile & 3) * CT_BUFSZ;

            unsigned kb8v[8];
            ldsm_x4(kb8v[0], kb8v[1], kb8v[2], kb8v[3],
                    &b_s[(t * 64 + r8) * 40 + 32]);
            ldsm_x4(kb8v[4], kb8v[5], kb8v[6], kb8v[7],
                    &b_s[(t * 64 + 32 + r8) * 40 + 32]);

            float S[8][4];
#pragma unroll
            for (int nt = 0; nt < 8; nt++)
#pragma unroll
                for (int q = 0; q < 4; q++) S[nt][q] = 0.f;

#pragma unroll
            for (int nt = 0; nt < 8; nt++) {
                unsigned kb0[2], kb1[2];
                ldsm_x4(kb0[0], kb1[0], kb0[1], kb1[1],
                        &b_s[(t * 64 + nt * 8 + l8) * 40 + mrow * 8]);
                mma16816(S[nt], qf[0], kb0[0], kb1[0]);
                mma16816(S[nt], qf[1], kb0[1], kb1[1]);
                mma16808(S[nt], qf8[0], qf8[1], kb8v[nt]);
            }

#pragma unroll
            for (int h2 = 0; h2 < 2; h2++) {
                float tm = -1e30f;
#pragma unroll
                for (int nt = 0; nt < 8; nt++)
                    tm = fmaxf(tm, fmaxf(S[nt][2 * h2], S[nt][2 * h2 + 1]));
                tm = fmaxf(tm, __shfl_xor_sync(0xffffffffu, tm, 1));
                tm = fmaxf(tm, __shfl_xor_sync(0xffffffffu, tm, 2));
                if (tm > m[h2]) {
                    float al = ex2f(m[h2] - tm);
                    m[h2] = tm;
                    l[h2] *= al;
#pragma unroll
                    for (int dt = 0; dt < 8; dt++) {
                        O[dt][2 * h2] *= al;
                        O[dt][2 * h2 + 1] *= al;
                    }
#pragma unroll
                    for (int n = 0; n < 6; n++) {
                        T[n][2 * h2] *= al;
                        T[n][2 * h2 + 1] *= al;
                    }
                }
            }

            unsigned pa[4][4];
#pragma unroll
            for (int nt = 0; nt < 8; nt++) {
                unsigned p01 = ex2h2(S[nt][0] - m[0], S[nt][1] - m[0]);
                unsigned p23 = ex2h2(S[nt][2] - m[1], S[nt][3] - m[1]);
                pa[nt >> 1][(nt & 1) * 2]     = p01;
                pa[nt >> 1][(nt & 1) * 2 + 1] = p23;
            }

#pragma unroll
            for (int n = 0; n < 6; n++) {
                unsigned vb0[4], vb1[4];
                const __half* va = &ct_t[(n * 8 + l8) * CTS + mrow * 8];
                ldsm_x4(vb0[0], vb1[0], vb0[1], vb1[1], va);
                ldsm_x4(vb0[2], vb1[2], vb0[3], vb1[3], va + 32);
#pragma unroll
                for (int kc = 0; kc < 4; kc++)
                    mma16816(T[n], pa[kc], vb0[kc], vb1[kc]);
            }

            if (t == 15) {
                unsigned at16[2][4], at8a, at8b;
#pragma unroll
                for (int kc = 0; kc < 2; kc++) {
                    at16[kc][0] = packh2(T[2 * kc][0],     T[2 * kc][1]);
                    at16[kc][1] = packh2(T[2 * kc][2],     T[2 * kc][3]);
                    at16[kc][2] = packh2(T[2 * kc + 1][0], T[2 * kc + 1][1]);
                    at16[kc][3] = packh2(T[2 * kc + 1][2], T[2 * kc + 1][3]);
                }
                at8a = packh2(T[4][0], T[4][1]);
                at8b = packh2(T[4][2], T[4][3]);

                unsigned wb8v[8];
                ldsm_x4(wb8v[0], wb8v[1], wb8v[2], wb8v[3],
                        &wv_s[r8 * 40 + 32]);
                ldsm_x4(wb8v[4], wb8v[5], wb8v[6], wb8v[7],
                        &wv_s[(32 + r8) * 40 + 32]);

#pragma unroll
                for (int dt = 0; dt < 8; dt++) {
                    unsigned wb0[2], wb1[2];
                    ldsm_x4(wb0[0], wb1[0], wb0[1], wb1[1],
                            &wv_s[(dt * 8 + l8) * 40 + mrow * 8]);
                    mma16816(O[dt], at16[0], wb0[0], wb1[0]);
                    mma16816(O[dt], at16[1], wb0[1], wb1[1]);
                    mma16808(O[dt], at8a, at8b, wb8v[dt]);
                }
                if (tig == 0) {
                    l[0] += T[5][0];
                    l[1] += T[5][2];
                }
#pragma unroll
                for (int n = 0; n < 6; n++)
#pragma unroll
                    for (int q = 0; q < 4; q++) T[n][q] = 0.f;
            }
        }
    }

#pragma unroll
    for (int h2 = 0; h2 < 2; h2++) {
        float lt = __shfl_sync(0xffffffffu, l[h2], lane & 28);
        float inv = 1.0f / lt;
        int n = n0 + w * 16 + gi + h2 * 8;
        __half* orow = g_attn16 + ((size_t)((b << 10) | n)) * 512 + h * 64;
#pragma unroll
        for (int dt = 0; dt < 8; dt++) {
            *reinterpret_cast<unsigned*>(orow + dt * 8 + tig * 2) =
                packh2(O[dt][2 * h2] * inv, O[dt][2 * h2 + 1] * inv);
        }
    }
}

// ---------------------------------------------------------------------------
// out_gemm v3: 3-buffer cp.async pipeline, one barrier per k-chunk.
// ---------------------------------------------------------------------------
__global__ __launch_bounds__(128) void out_gemm(
    const float* __restrict__ bo, float* __restrict__ out) {
    __shared__ __half sA2[3][64 * 72];
    __shared__ __half sB2[3][64 * 72];

    const int bm0 = blockIdx.x * 64;
    const int bn0 = blockIdx.y * 64;
    const int tid = threadIdx.x;
    const int w = tid >> 5, lane = tid & 31;
    const int gi = lane >> 2, tig = lane & 3;
    const int l8 = lane & 7, mrow = lane >> 3;

    float acc[8][4];
#pragma unroll
    for (int nt = 0; nt < 8; nt++)
#pragma unroll
        for (int q = 0; q < 4; q++) acc[nt][q] = 0.f;

    const int ar = (lane & 15);
    const int ac = (lane >> 4) * 8;

#pragma unroll
    for (int i = 0; i < 4; i++) {
        int idx = tid + i * 128;
        int r = idx >> 3, s = idx & 7;
        cp16(&sA2[0][r * 72 + s * 8], g_attn16 + (size_t)(bm0 + r) * 512 + s * 8);
        cp16(&sB2[0][r * 72 + s * 8], g_woT + (size_t)(bn0 + r) * 512 + s * 8);
    }
    asm volatile("cp.async.commit_group;\n");

    for (int kc = 0; kc < 8; kc++) {
        const int buf = kc % 3;
        if (kc + 1 < 8) {
            const int nb = (kc + 1) % 3;
#pragma unroll
            for (int i = 0; i < 4; i++) {
                int idx = tid + i * 128;
                int r = idx >> 3, s = idx & 7;
                cp16(&sA2[nb][r * 72 + s * 8],
                     g_attn16 + (size_t)(bm0 + r) * 512 + (kc + 1) * 64 + s * 8);
                cp16(&sB2[nb][r * 72 + s * 8],
                     g_woT + (size_t)(bn0 + r) * 512 + (kc + 1) * 64 + s * 8);
            }
            asm volatile("cp.async.commit_group;\n");
            asm volatile("cp.async.wait_group 1;\n");
        } else {
            asm volatile("cp.async.wait_group 0;\n");
        }
        __syncthreads();

        const int m0 = w * 16;
#pragma unroll
        for (int ksp = 0; ksp < 2; ksp++) {
            unsigned af0[4], af1[4];
            ldsm_x4(af0[0], af0[1], af0[2], af0[3],
                    &sA2[buf][(m0 + ar) * 72 + ksp * 32 + ac]);
            ldsm_x4(af1[0], af1[1], af1[2], af1[3],
                    &sA2[buf][(m0 + ar) * 72 + ksp * 32 + 16 + ac]);
#pragma unroll
            for (int nt = 0; nt < 8; nt++) {
                unsigned b0a, b1a, b0b, b1b;
                ldsm_x4(b0a, b1a, b0b, b1b,
                        &sB2[buf][(nt * 8 + l8) * 72 + ksp * 32 + mrow * 8]);
                mma16816(acc[nt], af0, b0a, b1a);
                mma16816(acc[nt], af1, b0b, b1b);
            }
        }
    }

    const int r0 = bm0 + w * 16 + gi;
#pragma unroll
    for (int nt = 0; nt < 8; nt++) {
        int col = bn0 + nt * 8 + tig * 2;
        float b0 = bo[col], b1 = bo[col + 1];
        float2 o0 = make_float2(acc[nt][0] + b0, acc[nt][1] + b1);
        float2 o1 = make_float2(acc[nt][2] + b0, acc[nt][3] + b1);
        *reinterpret_cast<float2*>(out + (size_t)r0 * 256 + col) = o0;
        *reinterpret_cast<float2*>(out + (size_t)(r0 + 8) * 256 + col) = o1;
    }
}

// ---------------------------------------------------------------------------
extern "C" void kernel_launch(void* const* d_in, const int* in_sizes, int n_in,
                              void* d_out, int out_size) {
    const float* x   = (const float*)d_in[0];
    const float* wq1 = (const float*)d_in[1];
    const float* wq2 = (const float*)d_in[2];
    const float* wk1 = (const float*)d_in[3];
    const float* wk2 = (const float*)d_in[4];
    const float* wv1 = (const float*)d_in[5];
    const float* wv2 = (const float*)d_in[6];
    const float* wo  = (const float*)d_in[7];
    const float* bo  = (const float*)d_in[8];
    float* out = (float*)d_out;

    cudaFuncSetAttribute(attn_kernel, cudaFuncAttributeMaxDynamicSharedMemorySize,
                         ATTN_SMEM);

    pre_kernel<<<106, 256>>>(wq1, wk1, wv1, wq2, wk2, wv2, wo);
    proj_mma<<<128, 128>>>(x);
    attn_kernel<<<dim3(64, 4), 256, ATTN_SMEM>>>();
    out_gemm<<<dim3(64, 4), 128>>>(bo, out);
}